// round 1
// baseline (speedup 1.0000x reference)
#include <cuda_runtime.h>
#include <cuda_bf16.h>
#include <cstdint>
#include <cstddef>

// Problem dims
#define BB 8
#define TT 256
#define UU 64
#define HH 640
#define VV 1025
#define M_TOTAL (BB*TT*UU)   // 131072
#define V_PAD 1152           // 9 * 128

// GEMM tiling
#define BM 128
#define BN 128
#define BKK 32
#define LDK 40               // BK + 8 halves pad (conflict-free ldmatrix)

// Scratch (static device allocation is the sanctioned path; no cudaMalloc)
__device__ __nv_bfloat16 g_Cmb[(size_t)M_TOTAL * HH];   // ~168 MB
__device__ __nv_bfloat16 g_Wb[(size_t)V_PAD * HH];      // ~1.5 MB

// ---------------------------------------------------------------------------
// Kernel 1: convert + pad W to bf16
// ---------------------------------------------------------------------------
__global__ void prep_w_kernel(const float* __restrict__ W) {
    int idx = blockIdx.x * blockDim.x + threadIdx.x;
    if (idx < V_PAD * HH) {
        int v = idx / HH;
        int h = idx - v * HH;
        float val = (v < VV) ? W[(size_t)v * HH + h] : 0.0f;
        g_Wb[idx] = __float2bfloat16(val);
    }
}

// ---------------------------------------------------------------------------
// Kernel 2: combined = tanh(enc[b,t,:] + dec[b,u,:]) -> bf16 scratch
// One block per row m; 160 threads, one float4 (4 h) each.
// ---------------------------------------------------------------------------
__global__ void __launch_bounds__(160) prep_combined_kernel(
    const float* __restrict__ enc, const float* __restrict__ dec) {
    int m = blockIdx.x;
    int b = m >> 14;           // / (T*U) = 16384
    int tu = m & 16383;
    int t = tu >> 6;
    int u = tu & 63;
    const float4* e = (const float4*)(enc + (size_t)(b * TT + t) * HH);
    const float4* d = (const float4*)(dec + (size_t)(b * UU + u) * HH);
    __nv_bfloat16* out = g_Cmb + (size_t)m * HH;

    int i = threadIdx.x;   // 0..159, H/4 = 160
    float4 ev = e[i];
    float4 dv = d[i];
    float r0 = tanhf(ev.x + dv.x);
    float r1 = tanhf(ev.y + dv.y);
    float r2 = tanhf(ev.z + dv.z);
    float r3 = tanhf(ev.w + dv.w);
    union { __nv_bfloat162 h2[2]; uint2 u2; } pk;
    pk.h2[0] = __floats2bfloat162_rn(r0, r1);
    pk.h2[1] = __floats2bfloat162_rn(r2, r3);
    ((uint2*)out)[i] = pk.u2;
}

// ---------------------------------------------------------------------------
// Kernel 3: GEMM  logits[m][v] = sum_h Cmb[m][h] * Wb[v][h] + bias[v]
// BM=128, BN=128, BK=32; 256 threads; mma.sync.m16n8k16 bf16, fp32 accum.
// ---------------------------------------------------------------------------
__device__ __forceinline__ uint32_t smem_u32(const void* p) {
    return (uint32_t)__cvta_generic_to_shared(p);
}

__global__ void __launch_bounds__(256) gemm_kernel(
    const float* __restrict__ bias, float* __restrict__ out) {
    __shared__ __nv_bfloat16 sA[BM * LDK];
    __shared__ __nv_bfloat16 sB[BN * LDK];
    __shared__ float sBias[BN];

    int tid = threadIdx.x;
    int n0 = blockIdx.x * BN;    // N tile (fast dim -> L2 reuse of A tile)
    int m0 = blockIdx.y * BM;

    if (tid < BN) {
        int v = n0 + tid;
        sBias[tid] = (v < VV) ? bias[v] : 0.0f;
    }

    const __nv_bfloat16* gA = g_Cmb + (size_t)m0 * HH;
    const __nv_bfloat16* gB = g_Wb + (size_t)n0 * HH;

    int w = tid >> 5;
    int lane = tid & 31;
    int wm = (w >> 2) * 64;      // warp m offset: 0 or 64
    int wn = (w & 3) * 32;       // warp n offset: 0..96
    int g = lane >> 2;
    int tig = lane & 3;

    float acc[4][4][4];
#pragma unroll
    for (int i = 0; i < 4; i++)
#pragma unroll
        for (int n = 0; n < 4; n++)
#pragma unroll
            for (int c = 0; c < 4; c++) acc[i][n][c] = 0.0f;

    uint32_t sA_base = smem_u32(sA);
    uint32_t sB_base = smem_u32(sB);

    // per-thread global->smem copy indices: 2 x uint4 per tile per buffer
    int idx0 = tid * 2;
    int row0 = idx0 >> 2, c40 = idx0 & 3;
    int idx1 = tid * 2 + 1;
    int row1 = idx1 >> 2, c41 = idx1 & 3;

    for (int k0 = 0; k0 < HH; k0 += BKK) {
        uint4 va0 = *(const uint4*)(gA + (size_t)row0 * HH + k0 + c40 * 8);
        uint4 vb0 = *(const uint4*)(gB + (size_t)row0 * HH + k0 + c40 * 8);
        uint4 va1 = *(const uint4*)(gA + (size_t)row1 * HH + k0 + c41 * 8);
        uint4 vb1 = *(const uint4*)(gB + (size_t)row1 * HH + k0 + c41 * 8);
        *(uint4*)(sA + row0 * LDK + c40 * 8) = va0;
        *(uint4*)(sB + row0 * LDK + c40 * 8) = vb0;
        *(uint4*)(sA + row1 * LDK + c41 * 8) = va1;
        *(uint4*)(sB + row1 * LDK + c41 * 8) = vb1;
        __syncthreads();

#pragma unroll
        for (int ks = 0; ks < 2; ks++) {
            uint32_t afr[4][4];
            uint32_t bfr[4][2];
#pragma unroll
            for (int i = 0; i < 4; i++) {
                int r = wm + i * 16 + (lane & 15);
                int cc = ks * 16 + (lane >> 4) * 8;
                uint32_t addr = sA_base + (uint32_t)(r * LDK + cc) * 2;
                asm volatile(
                    "ldmatrix.sync.aligned.m8n8.x4.shared.b16 {%0,%1,%2,%3}, [%4];\n"
                    : "=r"(afr[i][0]), "=r"(afr[i][1]), "=r"(afr[i][2]), "=r"(afr[i][3])
                    : "r"(addr));
            }
#pragma unroll
            for (int n = 0; n < 4; n++) {
                int r = wn + n * 8 + (lane & 7);
                int cc = ks * 16 + ((lane >> 3) & 1) * 8;
                uint32_t addr = sB_base + (uint32_t)(r * LDK + cc) * 2;
                asm volatile(
                    "ldmatrix.sync.aligned.m8n8.x2.shared.b16 {%0,%1}, [%2];\n"
                    : "=r"(bfr[n][0]), "=r"(bfr[n][1])
                    : "r"(addr));
            }
#pragma unroll
            for (int i = 0; i < 4; i++) {
#pragma unroll
                for (int n = 0; n < 4; n++) {
                    asm volatile(
                        "mma.sync.aligned.m16n8k16.row.col.f32.bf16.bf16.f32 "
                        "{%0,%1,%2,%3}, {%4,%5,%6,%7}, {%8,%9}, {%0,%1,%2,%3};\n"
                        : "+f"(acc[i][n][0]), "+f"(acc[i][n][1]),
                          "+f"(acc[i][n][2]), "+f"(acc[i][n][3])
                        : "r"(afr[i][0]), "r"(afr[i][1]), "r"(afr[i][2]), "r"(afr[i][3]),
                          "r"(bfr[n][0]), "r"(bfr[n][1]));
                }
            }
        }
        __syncthreads();
    }

    // Epilogue: +bias, guarded scalar stores (rows not 16B-aligned: V=1025)
#pragma unroll
    for (int i = 0; i < 4; i++) {
        int row = m0 + wm + i * 16 + g;
        size_t base0 = (size_t)row * VV;
        size_t base1 = (size_t)(row + 8) * VV;
#pragma unroll
        for (int n = 0; n < 4; n++) {
            int lcol = wn + n * 8 + 2 * tig;
            int col = n0 + lcol;
            if (col < VV) {
                float bz = sBias[lcol];
                out[base0 + col] = acc[i][n][0] + bz;
                out[base1 + col] = acc[i][n][2] + bz;
            }
            if (col + 1 < VV) {
                float bz = sBias[lcol + 1];
                out[base0 + col + 1] = acc[i][n][1] + bz;
                out[base1 + col + 1] = acc[i][n][3] + bz;
            }
        }
    }
}

// ---------------------------------------------------------------------------
// Kernel 4: in-place log_softmax over last dim (V=1025), one block per row.
// ---------------------------------------------------------------------------
__global__ void __launch_bounds__(256) lsm_kernel(float* __restrict__ out) {
    __shared__ float redbuf[8];
    float* row = out + (size_t)blockIdx.x * VV;
    int tid = threadIdx.x;

    float vals[5];
    int cnt = 0;
    float mx = -1e30f;
    for (int c = tid; c < VV; c += 256) {
        float v = row[c];
        vals[cnt++] = v;
        mx = fmaxf(mx, v);
    }
    // block max
#pragma unroll
    for (int o = 16; o > 0; o >>= 1) mx = fmaxf(mx, __shfl_xor_sync(0xFFFFFFFFu, mx, o));
    if ((tid & 31) == 0) redbuf[tid >> 5] = mx;
    __syncthreads();
    float bmx = redbuf[0];
#pragma unroll
    for (int i = 1; i < 8; i++) bmx = fmaxf(bmx, redbuf[i]);
    __syncthreads();

    float s = 0.0f;
    for (int i = 0; i < cnt; i++) s += __expf(vals[i] - bmx);
#pragma unroll
    for (int o = 16; o > 0; o >>= 1) s += __shfl_xor_sync(0xFFFFFFFFu, s, o);
    if ((tid & 31) == 0) redbuf[tid >> 5] = s;
    __syncthreads();
    float total = redbuf[0];
#pragma unroll
    for (int i = 1; i < 8; i++) total += redbuf[i];

    float lse = bmx + logf(total);
    cnt = 0;
    for (int c = tid; c < VV; c += 256) {
        row[c] = vals[cnt++] - lse;
    }
}

// ---------------------------------------------------------------------------
// Launch
// ---------------------------------------------------------------------------
extern "C" void kernel_launch(void* const* d_in, const int* in_sizes, int n_in,
                              void* d_out, int out_size) {
    (void)in_sizes; (void)n_in; (void)out_size;
    const float* enc  = (const float*)d_in[0];
    const float* dec  = (const float*)d_in[1];
    const float* W    = (const float*)d_in[2];
    const float* bias = (const float*)d_in[3];
    float* out = (float*)d_out;

    prep_w_kernel<<<(V_PAD * HH + 255) / 256, 256>>>(W);
    prep_combined_kernel<<<M_TOTAL, 160>>>(enc, dec);
    gemm_kernel<<<dim3(V_PAD / BN, M_TOTAL / BM), 256>>>(bias, out);
    lsm_kernel<<<M_TOTAL, 256>>>(out);
}

// round 2
// speedup vs baseline: 1.1871x; 1.1871x over previous
#include <cuda_runtime.h>
#include <cuda_bf16.h>
#include <cstdint>
#include <cstddef>

// Problem dims
#define BB 8
#define TT 256
#define UU 64
#define HH 640
#define VV 1025
#define M_TOTAL (BB*TT*UU)   // 131072
#define V_PAD 1152           // 9 * 128

// GEMM tiling
#define BM 128
#define BN 128
#define BKK 64
#define LDK 72               // BK + 8 halves pad (conflict-free ldmatrix, 144B rows)
#define STAGES 4
#define KTILES (HH / BKK)    // 10

// Scratch
__device__ __nv_bfloat16 g_Cmb[(size_t)M_TOTAL * HH];   // ~168 MB
__device__ __nv_bfloat16 g_Wb[(size_t)V_PAD * HH];      // ~1.5 MB

// ---------------------------------------------------------------------------
// Kernel 1: convert + pad W to bf16
// ---------------------------------------------------------------------------
__global__ void prep_w_kernel(const float* __restrict__ W) {
    int idx = blockIdx.x * blockDim.x + threadIdx.x;
    if (idx < V_PAD * HH) {
        int v = idx / HH;
        int h = idx - v * HH;
        float val = (v < VV) ? W[(size_t)v * HH + h] : 0.0f;
        g_Wb[idx] = __float2bfloat16(val);
    }
}

// ---------------------------------------------------------------------------
// Kernel 2: combined = tanh(enc[b,t,:] + dec[b,u,:]) -> bf16 scratch
// ---------------------------------------------------------------------------
__global__ void __launch_bounds__(160) prep_combined_kernel(
    const float* __restrict__ enc, const float* __restrict__ dec) {
    int m = blockIdx.x;
    int b = m >> 14;
    int tu = m & 16383;
    int t = tu >> 6;
    int u = tu & 63;
    const float4* e = (const float4*)(enc + (size_t)(b * TT + t) * HH);
    const float4* d = (const float4*)(dec + (size_t)(b * UU + u) * HH);
    __nv_bfloat16* out = g_Cmb + (size_t)m * HH;

    int i = threadIdx.x;
    float4 ev = e[i];
    float4 dv = d[i];
    float r0 = tanhf(ev.x + dv.x);
    float r1 = tanhf(ev.y + dv.y);
    float r2 = tanhf(ev.z + dv.z);
    float r3 = tanhf(ev.w + dv.w);
    union { __nv_bfloat162 h2[2]; uint2 u2; } pk;
    pk.h2[0] = __floats2bfloat162_rn(r0, r1);
    pk.h2[1] = __floats2bfloat162_rn(r2, r3);
    ((uint2*)out)[i] = pk.u2;
}

// ---------------------------------------------------------------------------
// Kernel 3: pipelined GEMM, cp.async 4-stage, mma.sync m16n8k16 bf16/f32
// ---------------------------------------------------------------------------
__device__ __forceinline__ uint32_t smem_u32(const void* p) {
    return (uint32_t)__cvta_generic_to_shared(p);
}

__device__ __forceinline__ void cpasync16(uint32_t saddr, const void* gptr) {
    asm volatile("cp.async.cg.shared.global [%0], [%1], 16;\n"
                 :: "r"(saddr), "l"(gptr));
}

extern __shared__ __nv_bfloat16 smem_dyn[];

__global__ void __launch_bounds__(256) gemm_kernel(
    const float* __restrict__ bias, float* __restrict__ out) {
    __shared__ float sBias[BN];

    const int tid = threadIdx.x;
    const int n0 = blockIdx.x * BN;
    const int m0 = blockIdx.y * BM;

    if (tid < BN) {
        int v = n0 + tid;
        sBias[tid] = (v < VV) ? bias[v] : 0.0f;
    }

    const __nv_bfloat16* gA = g_Cmb + (size_t)m0 * HH;
    const __nv_bfloat16* gB = g_Wb + (size_t)n0 * HH;

    const uint32_t sA_u = smem_u32(smem_dyn);
    const uint32_t sB_u = sA_u + STAGES * BM * LDK * 2;

    const int w = tid >> 5;
    const int lane = tid & 31;
    const int wm = (w >> 2) * 64;
    const int wn = (w & 3) * 32;
    const int g = lane >> 2;
    const int tig = lane & 3;

    float acc[4][4][4];
#pragma unroll
    for (int i = 0; i < 4; i++)
#pragma unroll
        for (int n = 0; n < 4; n++)
#pragma unroll
            for (int c = 0; c < 4; c++) acc[i][n][c] = 0.0f;

    // per-thread copy map: 4 x (16B A chunk + 16B B chunk) per stage
    // idx = tid + 256*j -> row = idx>>3 (0..127), col16 = idx&7 (0..7)
#define LOAD_TILE(s, k0)                                                      \
    {                                                                         \
        uint32_t sa = sA_u + (uint32_t)(s) * BM * LDK * 2;                    \
        uint32_t sb = sB_u + (uint32_t)(s) * BN * LDK * 2;                    \
        _Pragma("unroll")                                                     \
        for (int j = 0; j < 4; j++) {                                         \
            int idx = tid + 256 * j;                                          \
            int row = idx >> 3, c16 = idx & 7;                                \
            uint32_t so = (uint32_t)(row * LDK + c16 * 8) * 2;                \
            cpasync16(sa + so, gA + (size_t)row * HH + (k0) + c16 * 8);       \
            cpasync16(sb + so, gB + (size_t)row * HH + (k0) + c16 * 8);       \
        }                                                                     \
    }

    // prologue: stages 0..STAGES-2
#pragma unroll
    for (int s = 0; s < STAGES - 1; s++) {
        LOAD_TILE(s, s * BKK);
        asm volatile("cp.async.commit_group;\n");
    }

#pragma unroll 1
    for (int kt = 0; kt < KTILES; kt++) {
        asm volatile("cp.async.wait_group %0;\n" :: "n"(STAGES - 2));
        __syncthreads();

        int nt = kt + STAGES - 1;
        if (nt < KTILES) {
            LOAD_TILE(nt % STAGES, nt * BKK);
        }
        asm volatile("cp.async.commit_group;\n");

        const int cur = kt % STAGES;
        const uint32_t sa = sA_u + (uint32_t)cur * BM * LDK * 2;
        const uint32_t sb = sB_u + (uint32_t)cur * BN * LDK * 2;

#pragma unroll
        for (int kk = 0; kk < BKK / 16; kk++) {
            uint32_t afr[4][4];
            uint32_t bfr[4][2];
#pragma unroll
            for (int i = 0; i < 4; i++) {
                int r = wm + i * 16 + (lane & 15);
                int cc = kk * 16 + (lane >> 4) * 8;
                uint32_t addr = sa + (uint32_t)(r * LDK + cc) * 2;
                asm volatile(
                    "ldmatrix.sync.aligned.m8n8.x4.shared.b16 {%0,%1,%2,%3}, [%4];\n"
                    : "=r"(afr[i][0]), "=r"(afr[i][1]), "=r"(afr[i][2]), "=r"(afr[i][3])
                    : "r"(addr));
            }
#pragma unroll
            for (int n = 0; n < 4; n++) {
                int r = wn + n * 8 + (lane & 7);
                int cc = kk * 16 + ((lane >> 3) & 1) * 8;
                uint32_t addr = sb + (uint32_t)(r * LDK + cc) * 2;
                asm volatile(
                    "ldmatrix.sync.aligned.m8n8.x2.shared.b16 {%0,%1}, [%2];\n"
                    : "=r"(bfr[n][0]), "=r"(bfr[n][1])
                    : "r"(addr));
            }
#pragma unroll
            for (int i = 0; i < 4; i++) {
#pragma unroll
                for (int n = 0; n < 4; n++) {
                    asm volatile(
                        "mma.sync.aligned.m16n8k16.row.col.f32.bf16.bf16.f32 "
                        "{%0,%1,%2,%3}, {%4,%5,%6,%7}, {%8,%9}, {%0,%1,%2,%3};\n"
                        : "+f"(acc[i][n][0]), "+f"(acc[i][n][1]),
                          "+f"(acc[i][n][2]), "+f"(acc[i][n][3])
                        : "r"(afr[i][0]), "r"(afr[i][1]), "r"(afr[i][2]), "r"(afr[i][3]),
                          "r"(bfr[n][0]), "r"(bfr[n][1]));
                }
            }
        }
        __syncthreads();
    }

    // Epilogue: +bias, guarded scalar stores (V=1025 rows unaligned)
#pragma unroll
    for (int i = 0; i < 4; i++) {
        int row = m0 + wm + i * 16 + g;
        size_t base0 = (size_t)row * VV;
        size_t base1 = (size_t)(row + 8) * VV;
#pragma unroll
        for (int n = 0; n < 4; n++) {
            int lcol = wn + n * 8 + 2 * tig;
            int col = n0 + lcol;
            if (col < VV) {
                float bz = sBias[lcol];
                out[base0 + col] = acc[i][n][0] + bz;
                out[base1 + col] = acc[i][n][2] + bz;
            }
            if (col + 1 < VV) {
                float bz = sBias[lcol + 1];
                out[base0 + col + 1] = acc[i][n][1] + bz;
                out[base1 + col + 1] = acc[i][n][3] + bz;
            }
        }
    }
}

// ---------------------------------------------------------------------------
// Kernel 4: warp-per-row in-place log_softmax (V=1025)
// ---------------------------------------------------------------------------
__global__ void __launch_bounds__(256) lsm_kernel(float* __restrict__ out) {
    int row_id = blockIdx.x * 8 + (threadIdx.x >> 5);
    int lane = threadIdx.x & 31;
    float* row = out + (size_t)row_id * VV;

    float v[32];
    float mx = -1e30f;
#pragma unroll
    for (int i = 0; i < 32; i++) {
        v[i] = row[lane + 32 * i];
        mx = fmaxf(mx, v[i]);
    }
    float vlast = (lane == 0) ? row[1024] : -1e30f;
    mx = fmaxf(mx, vlast);
#pragma unroll
    for (int o = 16; o > 0; o >>= 1)
        mx = fmaxf(mx, __shfl_xor_sync(0xFFFFFFFFu, mx, o));

    float s = 0.0f;
#pragma unroll
    for (int i = 0; i < 32; i++) s += __expf(v[i] - mx);
    if (lane == 0) s += __expf(vlast - mx);
#pragma unroll
    for (int o = 16; o > 0; o >>= 1)
        s += __shfl_xor_sync(0xFFFFFFFFu, s, o);

    float lse = mx + logf(s);
#pragma unroll
    for (int i = 0; i < 32; i++) row[lane + 32 * i] = v[i] - lse;
    if (lane == 0) row[1024] = vlast - lse;
}

// ---------------------------------------------------------------------------
// Launch
// ---------------------------------------------------------------------------
extern "C" void kernel_launch(void* const* d_in, const int* in_sizes, int n_in,
                              void* d_out, int out_size) {
    (void)in_sizes; (void)n_in; (void)out_size;
    const float* enc  = (const float*)d_in[0];
    const float* dec  = (const float*)d_in[1];
    const float* W    = (const float*)d_in[2];
    const float* bias = (const float*)d_in[3];
    float* out = (float*)d_out;

    static int smem_set = 0;
    const int gemm_smem = STAGES * (BM + BN) * LDK * 2;  // 147456 B
    if (!smem_set) {
        cudaFuncSetAttribute(gemm_kernel,
                             cudaFuncAttributeMaxDynamicSharedMemorySize,
                             gemm_smem);
        smem_set = 1;
    }

    prep_w_kernel<<<(V_PAD * HH + 255) / 256, 256>>>(W);
    prep_combined_kernel<<<M_TOTAL, 160>>>(enc, dec);
    gemm_kernel<<<dim3(V_PAD / BN, M_TOTAL / BM), 256, gemm_smem>>>(bias, out);
    lsm_kernel<<<M_TOTAL / 8, 256>>>(out);
}